// round 1
// baseline (speedup 1.0000x reference)
#include <cuda_runtime.h>
#include <math.h>

#define TWO_N    512
#define DMODEL   256
#define NTHREADS 256
#define NWARPS   8

__global__ void supcr_zero_kernel(float* out) { *out = 0.0f; }

__global__ void __launch_bounds__(NTHREADS) supcr_kernel(
    const float* __restrict__ E,   // [512, 256]
    const float* __restrict__ T,   // [512]
    float* __restrict__ out)       // scalar
{
    __shared__ float sh_ei[DMODEL];
    __shared__ float sh_t[TWO_N];
    __shared__ float s_row[TWO_N];
    __shared__ float dist_row[TWO_N];
    __shared__ float a_row[TWO_N];
    __shared__ float keys[TWO_N];
    __shared__ float vals[TWO_N];
    __shared__ float sc0[TWO_N];
    __shared__ float sc1[TWO_N];
    __shared__ float red[NWARPS];

    const int i    = blockIdx.x;
    const int t    = threadIdx.x;
    const int lane = t & 31;
    const int wid  = t >> 5;

    // ---- load row i of E and all targets into SMEM ----
    sh_ei[t]      = E[i * DMODEL + t];
    sh_t[t]       = T[t];
    sh_t[t + 256] = T[t + 256];
    __syncthreads();

    const float ti = sh_t[i];
    const float4* ei4 = reinterpret_cast<const float4*>(sh_ei);

    // ---- phase 1: dist/s/a for all j; one warp per j, coalesced float4 reads ----
    for (int j = wid; j < TWO_N; j += NWARPS) {
        const float4* ej4 = reinterpret_cast<const float4*>(E + j * DMODEL);
        float acc = 0.0f;
        #pragma unroll
        for (int c = 0; c < 2; c++) {
            int d4 = lane + c * 32;
            float4 a = ei4[d4];
            float4 b = __ldg(&ej4[d4]);
            float dx = a.x - b.x, dy = a.y - b.y;
            float dz = a.z - b.z, dw = a.w - b.w;
            acc = fmaf(dx, dx, acc);
            acc = fmaf(dy, dy, acc);
            acc = fmaf(dz, dz, acc);
            acc = fmaf(dw, dw, acc);
        }
        #pragma unroll
        for (int o = 16; o > 0; o >>= 1)
            acc += __shfl_xor_sync(0xffffffffu, acc, o);
        if (lane == 0) {
            float dist = sqrtf(acc);
            dist_row[j] = dist;
            s_row[j]    = expf(-dist);
            a_row[j]    = fabsf(ti - sh_t[j]);
        }
    }
    __syncthreads();

    // ---- phase 2: bitonic sort 512 (key = a ascending, payload = s) ----
    keys[t]       = a_row[t];
    keys[t + 256] = a_row[t + 256];
    vals[t]       = s_row[t];
    vals[t + 256] = s_row[t + 256];
    __syncthreads();

    for (int k = 2; k <= TWO_N; k <<= 1) {
        for (int j = k >> 1; j > 0; j >>= 1) {
            #pragma unroll
            for (int c = 0; c < 2; c++) {
                int e = t + c * 256;
                int p = e ^ j;
                if (p > e) {
                    bool up = ((e & k) == 0);
                    float ka = keys[e], kb = keys[p];
                    if ((ka > kb) == up) {
                        keys[e] = kb; keys[p] = ka;
                        float va = vals[e];
                        vals[e] = vals[p]; vals[p] = va;
                    }
                }
            }
            __syncthreads();
        }
    }

    // ---- phase 3: suffix sums of sorted s (suffix direction => no cancellation) ----
    sc0[t]       = vals[t];
    sc0[t + 256] = vals[t + 256];
    __syncthreads();
    float* src = sc0;
    float* dst = sc1;
    for (int off = 1; off < TWO_N; off <<= 1) {
        #pragma unroll
        for (int c = 0; c < 2; c++) {
            int e = t + c * 256;
            float v = src[e];
            if (e + off < TWO_N) v += src[e + off];
            dst[e] = v;
        }
        __syncthreads();
        float* tmp = src; src = dst; dst = tmp;
    }
    // src[p] = sum_{q >= p} vals[q]

    // ---- phase 4: per-k denom via lower_bound + log; accumulate loss terms ----
    float local = 0.0f;
    #pragma unroll
    for (int c = 0; c < 2; c++) {
        int k = t + c * 256;
        if (k != i) {
            float ak = a_row[k];
            int lo = 0, hi = TWO_N;
            while (lo < hi) {
                int mid = (lo + hi) >> 1;
                if (keys[mid] < ak) lo = mid + 1; else hi = mid;
            }
            float denom = src[lo];          // sum over {j : a_j >= a_k}
            if (ak == 0.0f) denom -= 1.0f;  // drop self term s[i,i] = 1 (off_diag)
            local += dist_row[k] + logf(denom);
        }
    }

    // ---- phase 5: block reduce + scaled atomic into scalar output ----
    #pragma unroll
    for (int o = 16; o > 0; o >>= 1)
        local += __shfl_xor_sync(0xffffffffu, local, o);
    if (lane == 0) red[wid] = local;
    __syncthreads();
    if (t == 0) {
        float sum = 0.0f;
        #pragma unroll
        for (int w = 0; w < NWARPS; w++) sum += red[w];
        const float scale = 1.0f / (float(TWO_N) * float(TWO_N - 1));
        atomicAdd(out, sum * scale);
    }
}

extern "C" void kernel_launch(void* const* d_in, const int* in_sizes, int n_in,
                              void* d_out, int out_size) {
    const float* E = (const float*)d_in[0];   // embeddings [512,256] fp32
    const float* T = (const float*)d_in[1];   // targets    [512]     fp32
    float* out = (float*)d_out;

    supcr_zero_kernel<<<1, 1>>>(out);
    supcr_kernel<<<TWO_N, NTHREADS>>>(E, T, out);
}

// round 2
// speedup vs baseline: 2.2174x; 2.2174x over previous
#include <cuda_runtime.h>
#include <math.h>

#define N2 512
#define DM 256

// scratch (static device arrays — no allocation)
__device__ float g_dist[N2 * N2];
__device__ float g_ts[N2];
__device__ int   g_perm[N2];
__device__ float g_norm[N2];

// ---------------------------------------------------------------------------
// K1: rank-by-counting sort of targets + row norms + zero output
// grid = 64 blocks x 256 threads; block b handles elements b*8 + warp
// ---------------------------------------------------------------------------
__global__ void __launch_bounds__(256) prep_kernel(
    const float* __restrict__ E, const float* __restrict__ T, float* out)
{
    __shared__ float st[N2];
    const int t = threadIdx.x, lane = t & 31, w = t >> 5;
    st[t]       = T[t];
    st[t + 256] = T[t + 256];
    if (blockIdx.x == 0 && t == 0) *out = 0.0f;
    __syncthreads();

    const int e = blockIdx.x * 8 + w;
    const float tv = st[e];

    // rank of element e (ties broken by index -> valid permutation)
    int cnt = 0;
    #pragma unroll
    for (int c = 0; c < 16; c++) {
        int j = lane + c * 32;
        float o = st[j];
        cnt += (o < tv) || (o == tv && j < e);
    }
    #pragma unroll
    for (int o = 16; o > 0; o >>= 1) cnt += __shfl_xor_sync(0xffffffffu, cnt, o);

    // norm of row e
    const float4* er = reinterpret_cast<const float4*>(E + e * DM);
    float acc = 0.0f;
    #pragma unroll
    for (int c = 0; c < 2; c++) {
        float4 v = er[lane + c * 32];
        acc = fmaf(v.x, v.x, acc);
        acc = fmaf(v.y, v.y, acc);
        acc = fmaf(v.z, v.z, acc);
        acc = fmaf(v.w, v.w, acc);
    }
    #pragma unroll
    for (int o = 16; o > 0; o >>= 1) acc += __shfl_xor_sync(0xffffffffu, acc, o);

    if (lane == 0) {
        g_ts[cnt]   = tv;
        g_perm[cnt] = e;
        g_norm[e]   = acc;
    }
}

// ---------------------------------------------------------------------------
// K2: distance matrix via Gram trick.  D[i][j] = sqrt(max(ni + nj - 2*g, 0))
// grid = (16,16), block = (16,16); 32x32 tile, 2x2 microtile per thread
// ---------------------------------------------------------------------------
__global__ void __launch_bounds__(256) dist_kernel(const float* __restrict__ E)
{
    __shared__ float As[32][33];
    __shared__ float Bs[32][33];

    const int tx = threadIdx.x, ty = threadIdx.y;
    const int tid = ty * 16 + tx;
    const int bi = blockIdx.y * 32, bj = blockIdx.x * 32;

    float a00 = 0.f, a01 = 0.f, a10 = 0.f, a11 = 0.f;

    const int r = tid >> 3;          // 0..31
    const int c = (tid & 7) << 2;    // 0,4,...,28

    for (int k0 = 0; k0 < DM; k0 += 32) {
        float4 av = *reinterpret_cast<const float4*>(E + (bi + r) * DM + k0 + c);
        float4 bv = *reinterpret_cast<const float4*>(E + (bj + r) * DM + k0 + c);
        As[r][c] = av.x; As[r][c + 1] = av.y; As[r][c + 2] = av.z; As[r][c + 3] = av.w;
        Bs[r][c] = bv.x; Bs[r][c + 1] = bv.y; Bs[r][c + 2] = bv.z; Bs[r][c + 3] = bv.w;
        __syncthreads();
        #pragma unroll
        for (int kk = 0; kk < 32; kk++) {
            float x0 = As[ty * 2][kk],     x1 = As[ty * 2 + 1][kk];
            float y0 = Bs[tx * 2][kk],     y1 = Bs[tx * 2 + 1][kk];
            a00 = fmaf(x0, y0, a00);
            a01 = fmaf(x0, y1, a01);
            a10 = fmaf(x1, y0, a10);
            a11 = fmaf(x1, y1, a11);
        }
        __syncthreads();
    }

    const int i0 = bi + ty * 2, j0 = bj + tx * 2;
    const float n0 = g_norm[i0], n1 = g_norm[i0 + 1];
    const float m0 = g_norm[j0], m1 = g_norm[j0 + 1];
    g_dist[(i0    ) * N2 + j0    ] = sqrtf(fmaxf(n0 + m0 - 2.f * a00, 0.f));
    g_dist[(i0    ) * N2 + j0 + 1] = sqrtf(fmaxf(n0 + m1 - 2.f * a01, 0.f));
    g_dist[(i0 + 1) * N2 + j0    ] = sqrtf(fmaxf(n1 + m0 - 2.f * a10, 0.f));
    g_dist[(i0 + 1) * N2 + j0 + 1] = sqrtf(fmaxf(n1 + m1 - 2.f * a11, 0.f));
}

// ---------------------------------------------------------------------------
// K3: per-row loss. prefix+suffix scans of s in globally-sorted target order,
// binary searches replace per-row sort. grid = 512 x 256
// ---------------------------------------------------------------------------
__global__ void __launch_bounds__(256) loss_kernel(
    const float* __restrict__ T, float* __restrict__ out)
{
    __shared__ float drow[N2];
    __shared__ float st[N2];
    __shared__ float ts[N2];
    __shared__ float p0[N2], p1[N2], s0[N2], s1[N2];
    __shared__ float red[8];

    const int i = blockIdx.x, t = threadIdx.x, lane = t & 31, w = t >> 5;
    const float* Drow = g_dist + i * N2;

    #pragma unroll
    for (int c = 0; c < 2; c++) {
        int e = t + c * 256;
        drow[e] = Drow[e];
        st[e]   = T[e];
        ts[e]   = g_ts[e];
    }
    __syncthreads();

    const float ti = st[i];

    // s in sorted order (self term forced to exact 1.0)
    #pragma unroll
    for (int c = 0; c < 2; c++) {
        int e = t + c * 256;
        int p = g_perm[e];
        float s = (p == i) ? 1.0f : expf(-drow[p]);
        p0[e] = s;
        s0[e] = s;
    }
    __syncthreads();

    // simultaneous inclusive prefix + inclusive suffix scan (Hillis-Steele)
    float *ps = p0, *pd = p1, *ss = s0, *sd = s1;
    for (int off = 1; off < N2; off <<= 1) {
        #pragma unroll
        for (int c = 0; c < 2; c++) {
            int e = t + c * 256;
            float pv = ps[e]; if (e >= off)       pv += ps[e - off];
            float sv = ss[e]; if (e + off < N2)   sv += ss[e + off];
            pd[e] = pv;
            sd[e] = sv;
        }
        __syncthreads();
        float* tmp;
        tmp = ps; ps = pd; pd = tmp;
        tmp = ss; ss = sd; sd = tmp;
    }
    // ps[r] = sum_{q<=r} s_sorted, ss[r] = sum_{q>=r} s_sorted
    const float total = ps[N2 - 1];

    float local = 0.0f;
    #pragma unroll
    for (int c = 0; c < 2; c++) {
        int k = t + c * 256;
        if (k == i) continue;
        float ak = fabsf(ti - st[k]);
        float denom;
        if (ak == 0.0f) {
            denom = total - 1.0f;   // all j except self
        } else {
            // left tail: first L with fl(ti - ts[L]) < ak  (pred monotone down)
            int lo = 0, hi = N2;
            while (lo < hi) {
                int m = (lo + hi) >> 1;
                if (ti - ts[m] >= ak) lo = m + 1; else hi = m;
            }
            float dl = (lo > 0) ? ps[lo - 1] : 0.0f;
            // right tail: first R with fl(ts[R] - ti) >= ak (pred monotone up)
            int lo2 = 0, hi2 = N2;
            while (lo2 < hi2) {
                int m = (lo2 + hi2) >> 1;
                if (ts[m] - ti >= ak) hi2 = m; else lo2 = m + 1;
            }
            float dr = (lo2 < N2) ? ss[lo2] : 0.0f;
            denom = dl + dr;
        }
        local += drow[k] + logf(denom);
    }

    #pragma unroll
    for (int o = 16; o > 0; o >>= 1)
        local += __shfl_xor_sync(0xffffffffu, local, o);
    if (lane == 0) red[w] = local;
    __syncthreads();
    if (t == 0) {
        float sum = 0.0f;
        #pragma unroll
        for (int k = 0; k < 8; k++) sum += red[k];
        const float scale = 1.0f / (float(N2) * float(N2 - 1));
        atomicAdd(out, sum * scale);
    }
}

extern "C" void kernel_launch(void* const* d_in, const int* in_sizes, int n_in,
                              void* d_out, int out_size) {
    const float* E = (const float*)d_in[0];   // embeddings [512,256]
    const float* T = (const float*)d_in[1];   // targets    [512]
    float* out = (float*)d_out;

    prep_kernel<<<64, 256>>>(E, T, out);
    dist_kernel<<<dim3(16, 16), dim3(16, 16)>>>(E);
    loss_kernel<<<N2, 256>>>(T, out);
}

// round 3
// speedup vs baseline: 2.2667x; 1.0222x over previous
#include <cuda_runtime.h>
#include <math.h>

#define N2 512
#define DM 256

__device__ float g_dist[N2 * N2];
__device__ float g_ts[N2];
__device__ int   g_perm[N2];

// ---------------------------------------------------------------------------
// K1: 64x64-tile Gram GEMM -> distance matrix, with fused target ranking,
// fused row norms, and output zeroing.  grid (8,8) x 256 threads, 1 wave.
// ---------------------------------------------------------------------------
__global__ void __launch_bounds__(256) dist_kernel(
    const float* __restrict__ E, const float* __restrict__ T,
    float* __restrict__ out)
{
    __shared__ float At[32][68];   // [k][rotated row]
    __shared__ float Bt[32][68];
    __shared__ float nA[64], nB[64];

    const int tid  = threadIdx.x;
    const int lane = tid & 31;
    const int w    = tid >> 5;
    const int bi   = blockIdx.y * 64, bj = blockIdx.x * 64;
    const int bid  = blockIdx.y * 8 + blockIdx.x;

    if (bid == 0 && tid == 0) *out = 0.0f;

    // ---- fused rank-by-count: warp w ranks element e = bid*8 + w ----
    {
        const int e = bid * 8 + w;
        const float tv = __ldg(&T[e]);
        int cnt = 0;
        #pragma unroll
        for (int c = 0; c < 16; c++) {
            int jj = lane + c * 32;
            float o = __ldg(&T[jj]);
            cnt += (o < tv || (o == tv && jj < e)) ? 1 : 0;
        }
        #pragma unroll
        for (int o = 16; o > 0; o >>= 1) cnt += __shfl_xor_sync(0xffffffffu, cnt, o);
        if (lane == 0) { g_ts[cnt] = tv; g_perm[cnt] = e; }
    }

    // ---- GEMM thread mappings ----
    const int r   = tid >> 2;      // 0..63   (loader row)
    const int cq  = tid & 3;       // 0..3    (loader k-quarter)
    const int tx  = tid & 15, ty = tid >> 4;
    const int ty4 = ty * 4, tx4 = tx * 4;

    float acc[4][4];
    #pragma unroll
    for (int a = 0; a < 4; a++)
        #pragma unroll
        for (int b = 0; b < 4; b++) acc[a][b] = 0.0f;

    float pa = 0.0f, pb = 0.0f;

    const float* Ea = E + (bi + r) * DM;
    const float* Eb = E + (bj + r) * DM;

#define STORE_A(k, val) At[(k)][(r + 8 * ((k) >> 3)) & 63] = (val)
#define STORE_B(k, val) Bt[(k)][(r + 8 * ((k) >> 3)) & 63] = (val)

    for (int k0 = 0; k0 < DM; k0 += 32) {
        float4 a1 = *reinterpret_cast<const float4*>(Ea + k0 + cq * 4);
        float4 a2 = *reinterpret_cast<const float4*>(Ea + k0 + 16 + cq * 4);
        float4 b1 = *reinterpret_cast<const float4*>(Eb + k0 + cq * 4);
        float4 b2 = *reinterpret_cast<const float4*>(Eb + k0 + 16 + cq * 4);

        pa = fmaf(a1.x, a1.x, pa); pa = fmaf(a1.y, a1.y, pa);
        pa = fmaf(a1.z, a1.z, pa); pa = fmaf(a1.w, a1.w, pa);
        pa = fmaf(a2.x, a2.x, pa); pa = fmaf(a2.y, a2.y, pa);
        pa = fmaf(a2.z, a2.z, pa); pa = fmaf(a2.w, a2.w, pa);
        pb = fmaf(b1.x, b1.x, pb); pb = fmaf(b1.y, b1.y, pb);
        pb = fmaf(b1.z, b1.z, pb); pb = fmaf(b1.w, b1.w, pb);
        pb = fmaf(b2.x, b2.x, pb); pb = fmaf(b2.y, b2.y, pb);
        pb = fmaf(b2.z, b2.z, pb); pb = fmaf(b2.w, b2.w, pb);

        const int k1 = cq * 4, k2 = 16 + cq * 4;
        STORE_A(k1 + 0, a1.x); STORE_A(k1 + 1, a1.y);
        STORE_A(k1 + 2, a1.z); STORE_A(k1 + 3, a1.w);
        STORE_A(k2 + 0, a2.x); STORE_A(k2 + 1, a2.y);
        STORE_A(k2 + 2, a2.z); STORE_A(k2 + 3, a2.w);
        STORE_B(k1 + 0, b1.x); STORE_B(k1 + 1, b1.y);
        STORE_B(k1 + 2, b1.z); STORE_B(k1 + 3, b1.w);
        STORE_B(k2 + 0, b2.x); STORE_B(k2 + 1, b2.y);
        STORE_B(k2 + 2, b2.z); STORE_B(k2 + 3, b2.w);
        __syncthreads();

        #pragma unroll
        for (int kk = 0; kk < 32; kk++) {
            const int rot = 8 * (kk >> 3);
            float4 av = *reinterpret_cast<const float4*>(&At[kk][(ty4 + rot) & 63]);
            float4 bv = *reinterpret_cast<const float4*>(&Bt[kk][(tx4 + rot) & 63]);
            acc[0][0] = fmaf(av.x, bv.x, acc[0][0]);
            acc[0][1] = fmaf(av.x, bv.y, acc[0][1]);
            acc[0][2] = fmaf(av.x, bv.z, acc[0][2]);
            acc[0][3] = fmaf(av.x, bv.w, acc[0][3]);
            acc[1][0] = fmaf(av.y, bv.x, acc[1][0]);
            acc[1][1] = fmaf(av.y, bv.y, acc[1][1]);
            acc[1][2] = fmaf(av.y, bv.z, acc[1][2]);
            acc[1][3] = fmaf(av.y, bv.w, acc[1][3]);
            acc[2][0] = fmaf(av.z, bv.x, acc[2][0]);
            acc[2][1] = fmaf(av.z, bv.y, acc[2][1]);
            acc[2][2] = fmaf(av.z, bv.z, acc[2][2]);
            acc[2][3] = fmaf(av.z, bv.w, acc[2][3]);
            acc[3][0] = fmaf(av.w, bv.x, acc[3][0]);
            acc[3][1] = fmaf(av.w, bv.y, acc[3][1]);
            acc[3][2] = fmaf(av.w, bv.z, acc[3][2]);
            acc[3][3] = fmaf(av.w, bv.w, acc[3][3]);
        }
        __syncthreads();
    }

    // ---- fused row norms: reduce pa/pb across the 4 threads sharing row r ----
    pa += __shfl_xor_sync(0xffffffffu, pa, 1);
    pa += __shfl_xor_sync(0xffffffffu, pa, 2);
    pb += __shfl_xor_sync(0xffffffffu, pb, 1);
    pb += __shfl_xor_sync(0xffffffffu, pb, 2);
    if (cq == 0) { nA[r] = pa; nB[r] = pb; }
    __syncthreads();

    float na[4], nb[4];
    #pragma unroll
    for (int q = 0; q < 4; q++) { na[q] = nA[ty4 + q]; nb[q] = nB[tx4 + q]; }

    #pragma unroll
    for (int ri = 0; ri < 4; ri++) {
        float4 o;
        o.x = sqrtf(fmaxf(na[ri] + nb[0] - 2.0f * acc[ri][0], 0.0f));
        o.y = sqrtf(fmaxf(na[ri] + nb[1] - 2.0f * acc[ri][1], 0.0f));
        o.z = sqrtf(fmaxf(na[ri] + nb[2] - 2.0f * acc[ri][2], 0.0f));
        o.w = sqrtf(fmaxf(na[ri] + nb[3] - 2.0f * acc[ri][3], 0.0f));
        *reinterpret_cast<float4*>(&g_dist[(bi + ty4 + ri) * N2 + bj + tx4]) = o;
    }
}

// ---------------------------------------------------------------------------
// K2: per-row loss with warp-shuffle prefix+suffix scans (2 barriers)
// ---------------------------------------------------------------------------
__global__ void __launch_bounds__(256) loss_kernel(
    const float* __restrict__ T, float* __restrict__ out)
{
    __shared__ float drow[N2], st[N2], ts[N2], sv[N2], ps[N2], ss[N2];
    __shared__ float wtot[8];
    __shared__ float red[8];

    const int i = blockIdx.x, t = threadIdx.x, lane = t & 31, w = t >> 5;
    const float* Drow = g_dist + i * N2;

    #pragma unroll
    for (int c = 0; c < 2; c++) {
        int e = t + c * 256;
        drow[e] = Drow[e];
        st[e]   = T[e];
        ts[e]   = g_ts[e];
    }
    __syncthreads();

    const float ti = st[i];

    #pragma unroll
    for (int c = 0; c < 2; c++) {
        int e = t + c * 256;
        int p = g_perm[e];
        sv[e] = (p == i) ? 1.0f : expf(-drow[p]);
    }
    __syncthreads();

    // ---- warp-shuffle dual scan: thread owns elements 2t, 2t+1 ----
    const float v0 = sv[2 * t], v1 = sv[2 * t + 1];
    const float pair = v0 + v1;

    float p = pair;   // inclusive prefix of pair over lanes
    #pragma unroll
    for (int off = 1; off < 32; off <<= 1) {
        float tmp = __shfl_up_sync(0xffffffffu, p, off);
        if (lane >= off) p += tmp;
    }
    float q = pair;   // inclusive suffix of pair over lanes
    #pragma unroll
    for (int off = 1; off < 32; off <<= 1) {
        float tmp = __shfl_down_sync(0xffffffffu, q, off);
        if (lane + off < 32) q += tmp;
    }
    if (lane == 31) wtot[w] = p;
    __syncthreads();

    float offp = 0.0f, offs = 0.0f, total = 0.0f;
    #pragma unroll
    for (int ww = 0; ww < 8; ww++) {
        float tw = wtot[ww];
        total += tw;
        if (ww < w) offp += tw;
        if (ww > w) offs += tw;
    }
    ps[2 * t]     = offp + p - v1;
    ps[2 * t + 1] = offp + p;
    ss[2 * t]     = offs + q;
    ss[2 * t + 1] = offs + q - v0;
    __syncthreads();

    // ---- per-k denom via two binary searches ----
    float local = 0.0f;
    #pragma unroll
    for (int c = 0; c < 2; c++) {
        int k = t + c * 256;
        if (k == i) continue;
        float ak = fabsf(ti - st[k]);
        float denom;
        if (ak == 0.0f) {
            denom = total - 1.0f;
        } else {
            int lo = 0, hi = N2;            // first L with fl(ti - ts[L]) < ak
            while (lo < hi) {
                int m = (lo + hi) >> 1;
                if (ti - ts[m] >= ak) lo = m + 1; else hi = m;
            }
            float dl = (lo > 0) ? ps[lo - 1] : 0.0f;
            int lo2 = 0, hi2 = N2;          // first R with fl(ts[R] - ti) >= ak
            while (lo2 < hi2) {
                int m = (lo2 + hi2) >> 1;
                if (ts[m] - ti >= ak) hi2 = m; else lo2 = m + 1;
            }
            float dr = (lo2 < N2) ? ss[lo2] : 0.0f;
            denom = dl + dr;
        }
        local += drow[k] + logf(denom);
    }

    #pragma unroll
    for (int o = 16; o > 0; o >>= 1)
        local += __shfl_xor_sync(0xffffffffu, local, o);
    if (lane == 0) red[w] = local;
    __syncthreads();
    if (t == 0) {
        float sum = 0.0f;
        #pragma unroll
        for (int k = 0; k < 8; k++) sum += red[k];
        const float scale = 1.0f / (float(N2) * float(N2 - 1));
        atomicAdd(out, sum * scale);
    }
}

extern "C" void kernel_launch(void* const* d_in, const int* in_sizes, int n_in,
                              void* d_out, int out_size) {
    const float* E = (const float*)d_in[0];   // embeddings [512,256]
    const float* T = (const float*)d_in[1];   // targets    [512]
    float* out = (float*)d_out;

    dist_kernel<<<dim3(8, 8), 256>>>(E, T, out);
    loss_kernel<<<N2, 256>>>(T, out);
}

// round 4
// speedup vs baseline: 2.7568x; 1.2162x over previous
#include <cuda_runtime.h>
#include <math.h>

#define N2 512
#define DM 256
#define NTILE 16   // 512/32 tiles per dim; triangle count = 136

__device__ float g_dist[N2 * N2];
__device__ float g_ts[N2];
__device__ int   g_perm[N2];
__device__ float g_part[N2];

// ---------------------------------------------------------------------------
// K1: symmetric Gram GEMM over upper-triangle 32x32 tile pairs (136 blocks).
// Fused: target ranking (blocks 0..63), row norms. Writes tile + transpose.
// ---------------------------------------------------------------------------
__global__ void __launch_bounds__(256) dist_kernel(
    const float* __restrict__ E, const float* __restrict__ T)
{
    __shared__ float At[32][34];   // [k][row], pad 34 => float2-aligned, conflict-free
    __shared__ float Bt[32][34];
    __shared__ float nA[32], nB[32];

    const int tid = threadIdx.x, lane = tid & 31, w = tid >> 5;

    // map blockIdx.x -> (a,b), a <= b, over 16x16 tile grid
    int a = 0, rem = blockIdx.x, len = NTILE;
    while (rem >= len) { rem -= len; a++; len--; }
    const int b = a + rem;

    // ---- fused rank-by-count on blocks 0..63: warp w ranks e = bid*8+w ----
    if (blockIdx.x < 64) {
        const int e = blockIdx.x * 8 + w;
        const float tv = __ldg(&T[e]);
        int cnt = 0;
        #pragma unroll
        for (int c = 0; c < 16; c++) {
            int jj = lane + c * 32;
            float o = __ldg(&T[jj]);
            cnt += (o < tv || (o == tv && jj < e)) ? 1 : 0;
        }
        #pragma unroll
        for (int o = 16; o > 0; o >>= 1) cnt += __shfl_xor_sync(0xffffffffu, cnt, o);
        if (lane == 0) { g_ts[cnt] = tv; g_perm[cnt] = e; }
    }

    // ---- loader mapping: r = row in tile, cq*4 = k offset within chunk ----
    const int r  = tid >> 3;       // 0..31
    const int cq = tid & 7;        // 0..7
    const float* Ea = E + (a * 32 + r) * DM + cq * 4;
    const float* Eb = E + (b * 32 + r) * DM + cq * 4;

    const int tx = tid & 15, ty = tid >> 4;   // compute mapping (16x16, 2x2 micro)

    float a00 = 0.f, a01 = 0.f, a10 = 0.f, a11 = 0.f;
    float pa = 0.f, pb = 0.f;

    float4 av = *reinterpret_cast<const float4*>(Ea);
    float4 bv = *reinterpret_cast<const float4*>(Eb);

    for (int c = 0; c < 8; c++) {
        const int kb = cq * 4;
        At[kb + 0][r] = av.x; At[kb + 1][r] = av.y;
        At[kb + 2][r] = av.z; At[kb + 3][r] = av.w;
        Bt[kb + 0][r] = bv.x; Bt[kb + 1][r] = bv.y;
        Bt[kb + 2][r] = bv.z; Bt[kb + 3][r] = bv.w;
        pa = fmaf(av.x, av.x, pa); pa = fmaf(av.y, av.y, pa);
        pa = fmaf(av.z, av.z, pa); pa = fmaf(av.w, av.w, pa);
        pb = fmaf(bv.x, bv.x, pb); pb = fmaf(bv.y, bv.y, pb);
        pb = fmaf(bv.z, bv.z, pb); pb = fmaf(bv.w, bv.w, pb);
        __syncthreads();

        if (c < 7) {   // register prefetch of next chunk
            av = *reinterpret_cast<const float4*>(Ea + (c + 1) * 32);
            bv = *reinterpret_cast<const float4*>(Eb + (c + 1) * 32);
        }

        #pragma unroll
        for (int kk = 0; kk < 32; kk++) {
            float2 x = *reinterpret_cast<const float2*>(&At[kk][2 * ty]);
            float2 y = *reinterpret_cast<const float2*>(&Bt[kk][2 * tx]);
            a00 = fmaf(x.x, y.x, a00);
            a01 = fmaf(x.x, y.y, a01);
            a10 = fmaf(x.y, y.x, a10);
            a11 = fmaf(x.y, y.y, a11);
        }
        __syncthreads();
    }

    // ---- row norms: reduce over the 8 threads (cq) sharing row r ----
    pa += __shfl_xor_sync(0xffffffffu, pa, 1);
    pa += __shfl_xor_sync(0xffffffffu, pa, 2);
    pa += __shfl_xor_sync(0xffffffffu, pa, 4);
    pb += __shfl_xor_sync(0xffffffffu, pb, 1);
    pb += __shfl_xor_sync(0xffffffffu, pb, 2);
    pb += __shfl_xor_sync(0xffffffffu, pb, 4);
    if (cq == 0) { nA[r] = pa; nB[r] = pb; }
    __syncthreads();

    const float ni0 = nA[2 * ty], ni1 = nA[2 * ty + 1];
    const float nj0 = nB[2 * tx], nj1 = nB[2 * tx + 1];
    const float d00 = sqrtf(fmaxf(ni0 + nj0 - 2.f * a00, 0.f));
    const float d01 = sqrtf(fmaxf(ni0 + nj1 - 2.f * a01, 0.f));
    const float d10 = sqrtf(fmaxf(ni1 + nj0 - 2.f * a10, 0.f));
    const float d11 = sqrtf(fmaxf(ni1 + nj1 - 2.f * a11, 0.f));

    const int gi = a * 32 + 2 * ty, gj = b * 32 + 2 * tx;
    float2 v;
    v.x = d00; v.y = d01;
    *reinterpret_cast<float2*>(&g_dist[(gi    ) * N2 + gj]) = v;
    v.x = d10; v.y = d11;
    *reinterpret_cast<float2*>(&g_dist[(gi + 1) * N2 + gj]) = v;
    // transpose (identical values for diagonal blocks -> benign duplicate)
    v.x = d00; v.y = d10;
    *reinterpret_cast<float2*>(&g_dist[(gj    ) * N2 + gi]) = v;
    v.x = d01; v.y = d11;
    *reinterpret_cast<float2*>(&g_dist[(gj + 1) * N2 + gi]) = v;
}

// ---------------------------------------------------------------------------
// K2: per-row loss. Cancellation-free dual scan + binary searches.
// Writes partial sum per row (NO same-address atomics).
// ---------------------------------------------------------------------------
__global__ void __launch_bounds__(256) loss_kernel(const float* __restrict__ T)
{
    __shared__ float drow[N2], st[N2], ts[N2], sv[N2], ps[N2], ss[N2];
    __shared__ float wtot[8];
    __shared__ float red[8];

    const int i = blockIdx.x, t = threadIdx.x, lane = t & 31, w = t >> 5;
    const float* Drow = g_dist + i * N2;

    #pragma unroll
    for (int c = 0; c < 2; c++) {
        int e = t + c * 256;
        drow[e] = Drow[e];
        st[e]   = T[e];
        ts[e]   = g_ts[e];
    }
    __syncthreads();

    const float ti = st[i];

    #pragma unroll
    for (int c = 0; c < 2; c++) {
        int e = t + c * 256;
        int p = g_perm[e];
        sv[e] = (p == i) ? 1.0f : expf(-drow[p]);
    }
    __syncthreads();

    // ---- dual scan, additions only (thread owns elements 2t, 2t+1) ----
    const float v0 = sv[2 * t], v1 = sv[2 * t + 1];
    const float pair = v0 + v1;

    float p = pair;
    #pragma unroll
    for (int off = 1; off < 32; off <<= 1) {
        float tmp = __shfl_up_sync(0xffffffffu, p, off);
        if (lane >= off) p += tmp;
    }
    float q = pair;
    #pragma unroll
    for (int off = 1; off < 32; off <<= 1) {
        float tmp = __shfl_down_sync(0xffffffffu, q, off);
        if (lane + off < 32) q += tmp;
    }
    float pex = __shfl_up_sync(0xffffffffu, p, 1);
    if (lane == 0) pex = 0.0f;                 // exclusive pair prefix
    float sex = __shfl_down_sync(0xffffffffu, q, 1);
    if (lane == 31) sex = 0.0f;                // exclusive pair suffix
    if (lane == 31) wtot[w] = p;
    __syncthreads();

    float offp = 0.0f, offs = 0.0f, total = 0.0f;
    #pragma unroll
    for (int ww = 0; ww < 8; ww++) {
        float tw = wtot[ww];
        total += tw;
        if (ww < w) offp += tw;
        if (ww > w) offs += tw;
    }
    const float bp = offp + pex;
    const float bs = offs + sex;
    ps[2 * t]     = bp + v0;
    ps[2 * t + 1] = bp + v0 + v1;
    ss[2 * t + 1] = bs + v1;
    ss[2 * t]     = bs + v1 + v0;
    __syncthreads();

    // ---- per-k denom via two binary searches ----
    float local = 0.0f;
    #pragma unroll
    for (int c = 0; c < 2; c++) {
        int k = t + c * 256;
        if (k == i) continue;
        float ak = fabsf(ti - st[k]);
        float denom;
        if (ak == 0.0f) {
            denom = total - 1.0f;
        } else {
            int lo = 0, hi = N2;            // first L with fl(ti - ts[L]) < ak
            while (lo < hi) {
                int m = (lo + hi) >> 1;
                if (ti - ts[m] >= ak) lo = m + 1; else hi = m;
            }
            float dl = (lo > 0) ? ps[lo - 1] : 0.0f;
            int lo2 = 0, hi2 = N2;          // first R with fl(ts[R] - ti) >= ak
            while (lo2 < hi2) {
                int m = (lo2 + hi2) >> 1;
                if (ts[m] - ti >= ak) hi2 = m; else lo2 = m + 1;
            }
            float dr = (lo2 < N2) ? ss[lo2] : 0.0f;
            denom = dl + dr;
        }
        local += drow[k] + logf(denom);
    }

    #pragma unroll
    for (int o = 16; o > 0; o >>= 1)
        local += __shfl_xor_sync(0xffffffffu, local, o);
    if (lane == 0) red[w] = local;
    __syncthreads();
    if (t == 0) {
        float sum = 0.0f;
        #pragma unroll
        for (int k = 0; k < 8; k++) sum += red[k];
        g_part[i] = sum;                    // plain store, no atomic
    }
}

// ---------------------------------------------------------------------------
// K3: final reduce of 512 partials -> scalar
// ---------------------------------------------------------------------------
__global__ void __launch_bounds__(256) reduce_kernel(float* __restrict__ out)
{
    __shared__ float red[8];
    const int t = threadIdx.x, lane = t & 31, w = t >> 5;
    float v = g_part[t] + g_part[t + 256];
    #pragma unroll
    for (int o = 16; o > 0; o >>= 1)
        v += __shfl_xor_sync(0xffffffffu, v, o);
    if (lane == 0) red[w] = v;
    __syncthreads();
    if (t == 0) {
        float sum = 0.0f;
        #pragma unroll
        for (int k = 0; k < 8; k++) sum += red[k];
        const float scale = 1.0f / (float(N2) * float(N2 - 1));
        *out = sum * scale;
    }
}

extern "C" void kernel_launch(void* const* d_in, const int* in_sizes, int n_in,
                              void* d_out, int out_size) {
    const float* E = (const float*)d_in[0];   // embeddings [512,256]
    const float* T = (const float*)d_in[1];   // targets    [512]
    float* out = (float*)d_out;

    dist_kernel<<<136, 256>>>(E, T);
    loss_kernel<<<N2, 256>>>(T);
    reduce_kernel<<<1, 256>>>(out);
}

// round 5
// speedup vs baseline: 2.8041x; 1.0172x over previous
#include <cuda_runtime.h>
#include <math.h>

#define N2 512
#define DM 256
#define NSPLIT 8
#define KS 32        // k-width per split block
#define NT8 8        // 8 tiles of 64 per dim; triangle pairs = 36

__device__ float g_gram[NSPLIT][N2 * N2];   // partial Gram sums
__device__ float g_norm[N2];
__device__ float g_ts[N2];
__device__ int   g_perm[N2];
__device__ float g_part[N2];

// ---------------------------------------------------------------------------
// K1: split-k symmetric Gram GEMM. 36 tile-pairs (64x64) x 8 k-splits = 288
// blocks x 256 threads. 4x4 microtile, rotated-transpose SMEM (conflict-free).
// Blocks 0..63 additionally compute target ranks + row norms (warp/element).
// ---------------------------------------------------------------------------
__global__ void __launch_bounds__(256) dist_kernel(
    const float* __restrict__ E, const float* __restrict__ T)
{
    __shared__ float At[KS][68];
    __shared__ float Bt[KS][68];

    const int tid  = threadIdx.x;
    const int lane = tid & 31;
    const int w    = tid >> 5;

    // ---- fused rank-by-count + row norm on blocks 0..63 ----
    if (blockIdx.x < 64) {
        const int e = blockIdx.x * 8 + w;
        const float tv = __ldg(&T[e]);
        int cnt = 0;
        #pragma unroll
        for (int c = 0; c < 16; c++) {
            int jj = lane + c * 32;
            float o = __ldg(&T[jj]);
            cnt += (o < tv || (o == tv && jj < e)) ? 1 : 0;
        }
        float nrm = 0.0f;
        #pragma unroll
        for (int c = 0; c < 8; c++) {
            float v = __ldg(&E[e * DM + lane + c * 32]);
            nrm = fmaf(v, v, nrm);
        }
        #pragma unroll
        for (int o = 16; o > 0; o >>= 1) {
            cnt += __shfl_xor_sync(0xffffffffu, cnt, o);
            nrm += __shfl_xor_sync(0xffffffffu, nrm, o);
        }
        if (lane == 0) { g_ts[cnt] = tv; g_perm[cnt] = e; g_norm[e] = nrm; }
    }

    // ---- decode block -> (tile pair, k split) ----
    const int pair  = blockIdx.x >> 3;
    const int split = blockIdx.x & 7;
    int a = 0, rem = pair, len = NT8;
    while (rem >= len) { rem -= len; a++; len--; }
    const int b = a + rem;
    const int kbase = split * KS;

    // ---- loaders: r = row in 64-tile, cq = k quarter ----
    const int r  = tid >> 2;     // 0..63
    const int cq = tid & 3;      // 0..3
    const float* Ea = E + (a * 64 + r) * DM + kbase;
    const float* Eb = E + (b * 64 + r) * DM + kbase;

    float4 a1 = *reinterpret_cast<const float4*>(Ea + cq * 4);
    float4 a2 = *reinterpret_cast<const float4*>(Ea + 16 + cq * 4);
    float4 b1 = *reinterpret_cast<const float4*>(Eb + cq * 4);
    float4 b2 = *reinterpret_cast<const float4*>(Eb + 16 + cq * 4);

#define STORE_A(k, val) At[(k)][(r + 8 * ((k) >> 3)) & 63] = (val)
#define STORE_B(k, val) Bt[(k)][(r + 8 * ((k) >> 3)) & 63] = (val)
    {
        const int k1 = cq * 4, k2 = 16 + cq * 4;
        STORE_A(k1 + 0, a1.x); STORE_A(k1 + 1, a1.y);
        STORE_A(k1 + 2, a1.z); STORE_A(k1 + 3, a1.w);
        STORE_A(k2 + 0, a2.x); STORE_A(k2 + 1, a2.y);
        STORE_A(k2 + 2, a2.z); STORE_A(k2 + 3, a2.w);
        STORE_B(k1 + 0, b1.x); STORE_B(k1 + 1, b1.y);
        STORE_B(k1 + 2, b1.z); STORE_B(k1 + 3, b1.w);
        STORE_B(k2 + 0, b2.x); STORE_B(k2 + 1, b2.y);
        STORE_B(k2 + 2, b2.z); STORE_B(k2 + 3, b2.w);
    }
    __syncthreads();

    const int tx = tid & 15, ty = tid >> 4;
    const int ty4 = ty * 4, tx4 = tx * 4;

    float acc[4][4];
    #pragma unroll
    for (int x = 0; x < 4; x++)
        #pragma unroll
        for (int y = 0; y < 4; y++) acc[x][y] = 0.0f;

    #pragma unroll
    for (int kk = 0; kk < KS; kk++) {
        const int rot = 8 * (kk >> 3);
        float4 av = *reinterpret_cast<const float4*>(&At[kk][(ty4 + rot) & 63]);
        float4 bv = *reinterpret_cast<const float4*>(&Bt[kk][(tx4 + rot) & 63]);
        acc[0][0] = fmaf(av.x, bv.x, acc[0][0]);
        acc[0][1] = fmaf(av.x, bv.y, acc[0][1]);
        acc[0][2] = fmaf(av.x, bv.z, acc[0][2]);
        acc[0][3] = fmaf(av.x, bv.w, acc[0][3]);
        acc[1][0] = fmaf(av.y, bv.x, acc[1][0]);
        acc[1][1] = fmaf(av.y, bv.y, acc[1][1]);
        acc[1][2] = fmaf(av.y, bv.z, acc[1][2]);
        acc[1][3] = fmaf(av.y, bv.w, acc[1][3]);
        acc[2][0] = fmaf(av.z, bv.x, acc[2][0]);
        acc[2][1] = fmaf(av.z, bv.y, acc[2][1]);
        acc[2][2] = fmaf(av.z, bv.z, acc[2][2]);
        acc[2][3] = fmaf(av.z, bv.w, acc[2][3]);
        acc[3][0] = fmaf(av.w, bv.x, acc[3][0]);
        acc[3][1] = fmaf(av.w, bv.y, acc[3][1]);
        acc[3][2] = fmaf(av.w, bv.z, acc[3][2]);
        acc[3][3] = fmaf(av.w, bv.w, acc[3][3]);
    }

    // ---- write partial tile + its transpose (plain stores, deterministic) ----
    float* G = g_gram[split];
    const int gi = a * 64 + ty4, gj = b * 64 + tx4;
    #pragma unroll
    for (int ri = 0; ri < 4; ri++) {
        float4 o;
        o.x = acc[ri][0]; o.y = acc[ri][1]; o.z = acc[ri][2]; o.w = acc[ri][3];
        *reinterpret_cast<float4*>(&G[(gi + ri) * N2 + gj]) = o;
    }
    #pragma unroll
    for (int ci = 0; ci < 4; ci++) {
        float4 tr;
        tr.x = acc[0][ci]; tr.y = acc[1][ci]; tr.z = acc[2][ci]; tr.w = acc[3][ci];
        *reinterpret_cast<float4*>(&G[(gj + ci) * N2 + gi]) = tr;
    }
}

// ---------------------------------------------------------------------------
// K2: per-row loss. Assembles dist from split Gram partials + norms, then
// cancellation-free dual scan + binary searches. Plain per-row output store.
// ---------------------------------------------------------------------------
__global__ void __launch_bounds__(256) loss_kernel(const float* __restrict__ T)
{
    __shared__ float drow[N2], st[N2], ts[N2], sv[N2], ps[N2], ss[N2];
    __shared__ float wtot[8];
    __shared__ float red[8];

    const int i = blockIdx.x, t = threadIdx.x, lane = t & 31, w = t >> 5;
    const float ni = __ldg(&g_norm[i]);

    #pragma unroll
    for (int c = 0; c < 2; c++) {
        int e = t + c * 256;
        float gsum = 0.0f;
        #pragma unroll
        for (int s = 0; s < NSPLIT; s++)
            gsum += __ldg(&g_gram[s][i * N2 + e]);
        float ne = __ldg(&g_norm[e]);
        drow[e] = sqrtf(fmaxf(ni + ne - 2.0f * gsum, 0.0f));
        st[e]   = T[e];
        ts[e]   = g_ts[e];
    }
    __syncthreads();

    const float ti = st[i];

    #pragma unroll
    for (int c = 0; c < 2; c++) {
        int e = t + c * 256;
        int p = g_perm[e];
        sv[e] = (p == i) ? 1.0f : expf(-drow[p]);
    }
    __syncthreads();

    // ---- dual scan, additions only (thread owns elements 2t, 2t+1) ----
    const float v0 = sv[2 * t], v1 = sv[2 * t + 1];
    const float pair = v0 + v1;

    float p = pair;
    #pragma unroll
    for (int off = 1; off < 32; off <<= 1) {
        float tmp = __shfl_up_sync(0xffffffffu, p, off);
        if (lane >= off) p += tmp;
    }
    float q = pair;
    #pragma unroll
    for (int off = 1; off < 32; off <<= 1) {
        float tmp = __shfl_down_sync(0xffffffffu, q, off);
        if (lane + off < 32) q += tmp;
    }
    float pex = __shfl_up_sync(0xffffffffu, p, 1);
    if (lane == 0) pex = 0.0f;
    float sex = __shfl_down_sync(0xffffffffu, q, 1);
    if (lane == 31) sex = 0.0f;
    if (lane == 31) wtot[w] = p;
    __syncthreads();

    float offp = 0.0f, offs = 0.0f, total = 0.0f;
    #pragma unroll
    for (int ww = 0; ww < 8; ww++) {
        float tw = wtot[ww];
        total += tw;
        if (ww < w) offp += tw;
        if (ww > w) offs += tw;
    }
    const float bp = offp + pex;
    const float bs = offs + sex;
    ps[2 * t]     = bp + v0;
    ps[2 * t + 1] = bp + v0 + v1;
    ss[2 * t + 1] = bs + v1;
    ss[2 * t]     = bs + v1 + v0;
    __syncthreads();

    // ---- per-k denom via two binary searches ----
    float local = 0.0f;
    #pragma unroll
    for (int c = 0; c < 2; c++) {
        int k = t + c * 256;
        if (k == i) continue;
        float ak = fabsf(ti - st[k]);
        float denom;
        if (ak == 0.0f) {
            denom = total - 1.0f;
        } else {
            int lo = 0, hi = N2;            // first L with fl(ti - ts[L]) < ak
            while (lo < hi) {
                int m = (lo + hi) >> 1;
                if (ti - ts[m] >= ak) lo = m + 1; else hi = m;
            }
            float dl = (lo > 0) ? ps[lo - 1] : 0.0f;
            int lo2 = 0, hi2 = N2;          // first R with fl(ts[R] - ti) >= ak
            while (lo2 < hi2) {
                int m = (lo2 + hi2) >> 1;
                if (ts[m] - ti >= ak) hi2 = m; else lo2 = m + 1;
            }
            float dr = (lo2 < N2) ? ss[lo2] : 0.0f;
            denom = dl + dr;
        }
        local += drow[k] + logf(denom);
    }

    #pragma unroll
    for (int o = 16; o > 0; o >>= 1)
        local += __shfl_xor_sync(0xffffffffu, local, o);
    if (lane == 0) red[w] = local;
    __syncthreads();
    if (t == 0) {
        float sum = 0.0f;
        #pragma unroll
        for (int k = 0; k < 8; k++) sum += red[k];
        g_part[i] = sum;
    }
}

// ---------------------------------------------------------------------------
// K3: final reduce of 512 partials -> scalar
// ---------------------------------------------------------------------------
__global__ void __launch_bounds__(256) reduce_kernel(float* __restrict__ out)
{
    __shared__ float red[8];
    const int t = threadIdx.x, lane = t & 31, w = t >> 5;
    float v = g_part[t] + g_part[t + 256];
    #pragma unroll
    for (int o = 16; o > 0; o >>= 1)
        v += __shfl_xor_sync(0xffffffffu, v, o);
    if (lane == 0) red[w] = v;
    __syncthreads();
    if (t == 0) {
        float sum = 0.0f;
        #pragma unroll
        for (int k = 0; k < 8; k++) sum += red[k];
        const float scale = 1.0f / (float(N2) * float(N2 - 1));
        *out = sum * scale;
    }
}

extern "C" void kernel_launch(void* const* d_in, const int* in_sizes, int n_in,
                              void* d_out, int out_size) {
    const float* E = (const float*)d_in[0];   // embeddings [512,256]
    const float* T = (const float*)d_in[1];   // targets    [512]
    float* out = (float*)d_out;

    dist_kernel<<<36 * NSPLIT, 256>>>(E, T);
    loss_kernel<<<N2, 256>>>(T);
    reduce_kernel<<<1, 256>>>(out);
}